// round 13
// baseline (speedup 1.0000x reference)
#include <cuda_runtime.h>

#define IN_FEATURES 8192
#define OUT_FEATURES 8192
#define THREADS 256
#define NWARPS (THREADS / 32)
#define F4_PER_ROW (IN_FEATURES / 4)          // 2048
#define F4_PER_THREAD (F4_PER_ROW / THREADS)  // 8
#define GRID 456                              // ~3 CTAs/SM on 152-SM GB300

__global__ __launch_bounds__(THREADS, 2)
void snn_fused_kernel(const float* __restrict__ x,
                      const float* __restrict__ states,
                      const float* __restrict__ mp,
                      const float* __restrict__ thr,
                      const float* __restrict__ trace,
                      float* __restrict__ out) {
    __shared__ float4 sx[F4_PER_ROW];       // 32 KB staged spike input (once per CTA)
    __shared__ float warp_dot[2][NWARPS];   // double-buffered partials
    __shared__ float warp_wsum[2][NWARPS];

    const int tid  = threadIdx.x;
    const int lane = tid & 31;
    const int wid  = tid >> 5;

    // Stage x once per persistent CTA.
    const float4* x4 = reinterpret_cast<const float4*>(x);
    #pragma unroll
    for (int j = 0; j < F4_PER_THREAD; j++) {
        sx[tid + j * THREADS] = x4[tid + j * THREADS];
    }
    __syncthreads();

    int parity = 0;
    for (int o = blockIdx.x; o < OUT_FEATURES; o += GRID, parity ^= 1) {
        // Hoist scalar epilogue inputs ahead of phase 1 (independent loads).
        const float mp_o  = __ldg(&mp[o]);
        const float thr_o = __ldg(&thr[o]);

        // ---- Phase 1: binary-weight dot product + connection count ----
        const float4* st4 = reinterpret_cast<const float4*>(states + (size_t)o * IN_FEATURES);
        float dot = 0.0f, wsum = 0.0f;
        #pragma unroll
        for (int j = 0; j < F4_PER_THREAD; j++) {
            const int i = tid + j * THREADS;
            float4 s  = st4[i];
            float4 xv = sx[i];
            float w0 = (s.x > 50.0f) ? 1.0f : 0.0f;
            float w1 = (s.y > 50.0f) ? 1.0f : 0.0f;
            float w2 = (s.z > 50.0f) ? 1.0f : 0.0f;
            float w3 = (s.w > 50.0f) ? 1.0f : 0.0f;
            dot  += w0 * xv.x + w1 * xv.y + w2 * xv.z + w3 * xv.w;
            wsum += w0 + w1 + w2 + w3;
        }

        // Warp reduce
        #pragma unroll
        for (int off = 16; off > 0; off >>= 1) {
            dot  += __shfl_xor_sync(0xFFFFFFFFu, dot,  off);
            wsum += __shfl_xor_sync(0xFFFFFFFFu, wsum, off);
        }
        if (lane == 0) { warp_dot[parity][wid] = dot; warp_wsum[parity][wid] = wsum; }
        __syncthreads();   // one barrier per row (double-buffered partials
                           // make the WAR hazard two-barriers distant)

        // All-thread redundant final reduce + epilogue (pure smem + ALU).
        float d = 0.0f, ws = 0.0f;
        #pragma unroll
        for (int w = 0; w < NWARPS; w++) { d += warp_dot[parity][w]; ws += warp_wsum[parity][w]; }
        const float conn    = fmaxf(ws, 5.0f);
        const float current = d * (15.0f * rsqrtf(conn));
        const float v_mem   = mp_o * 0.85f + current;
        const float spike   = (v_mem >= thr_o) ? 1.0f : 0.0f;
        if (tid == 0) {
            const float new_v = v_mem * (1.0f - spike) * 0.1f;
            const float new_t = fminf(fmaxf(thr_o + (spike - 0.1f) * 0.1f, 2.0f), 15.0f);
            out[o]                    = spike;   // spikes
            out[OUT_FEATURES + o]     = new_v;   // new membrane potential
            out[2 * OUT_FEATURES + o] = new_t;   // new adaptive threshold
        }

        // ---- Phase 2: eligibility-trace update ----
        const float4* tr4 = reinterpret_cast<const float4*>(trace + (size_t)o * IN_FEATURES);
        float4* ot4 = reinterpret_cast<float4*>(out + 3 * (size_t)OUT_FEATURES + (size_t)o * IN_FEATURES);
        #pragma unroll
        for (int j = 0; j < F4_PER_THREAD; j++) {
            const int i = tid + j * THREADS;
            float4 t  = tr4[i];
            float4 xv = sx[i];
            float4 r;
            r.x = fminf(fmaxf(t.x * 0.9f + spike * xv.x, 0.0f), 5.0f);
            r.y = fminf(fmaxf(t.y * 0.9f + spike * xv.y, 0.0f), 5.0f);
            r.z = fminf(fmaxf(t.z * 0.9f + spike * xv.z, 0.0f), 5.0f);
            r.w = fminf(fmaxf(t.w * 0.9f + spike * xv.w, 0.0f), 5.0f);
            __stcs(&ot4[i], r);
        }
    }
}

extern "C" void kernel_launch(void* const* d_in, const int* in_sizes, int n_in,
                              void* d_out, int out_size) {
    const float* x      = (const float*)d_in[0];   // spike_input [8192]
    const float* states = (const float*)d_in[1];   // synapse_states [8192,8192]
    const float* mp     = (const float*)d_in[2];   // membrane_potential [8192]
    const float* thr    = (const float*)d_in[3];   // adaptive_threshold [8192]
    const float* trace  = (const float*)d_in[4];   // eligibility_trace [8192,8192]
    float* out          = (float*)d_out;

    snn_fused_kernel<<<GRID, THREADS>>>(x, states, mp, thr, trace, out);
}

// round 14
// speedup vs baseline: 1.0987x; 1.0987x over previous
#include <cuda_runtime.h>

#define IN_FEATURES 8192
#define OUT_FEATURES 8192
#define THREADS 256
#define NWARPS (THREADS / 32)
#define F4_PER_ROW (IN_FEATURES / 4)          // 2048
#define F4_PER_THREAD (F4_PER_ROW / THREADS)  // 8

__global__ __launch_bounds__(THREADS, 2)
void snn_fused_kernel(const float* __restrict__ x,
                      const float* __restrict__ states,
                      const float* __restrict__ mp,
                      const float* __restrict__ thr,
                      const float* __restrict__ trace,
                      float* __restrict__ out) {
    __shared__ float4 sx[F4_PER_ROW];   // 32 KB staged spike input
    __shared__ float warp_dot[NWARPS];
    __shared__ float warp_wsum[NWARPS];

    const int o   = blockIdx.x;
    const int tid = threadIdx.x;

    // ---- L2 prefetch of this row's trace data: one 128B line per thread
    // covers the whole 32 KB row. No destination register, cannot be sunk,
    // no LDGSTS issue cost. DRAM->L2 fetch overlaps phase 1 + barrier. ----
    const char* tr_row = reinterpret_cast<const char*>(trace + (size_t)o * IN_FEATURES);
    asm volatile("prefetch.global.L2 [%0];" :: "l"(tr_row + (size_t)tid * 128) : "memory");

    // Hoist scalar epilogue inputs (independent; ptxas won't hoist them
    // across the BAR.SYNC if left in the epilogue).
    const float mp_o  = __ldg(&mp[o]);
    const float thr_o = __ldg(&thr[o]);

    // Stage x into shared memory (L2-resident broadcast).
    const float4* x4 = reinterpret_cast<const float4*>(x);
    #pragma unroll
    for (int j = 0; j < F4_PER_THREAD; j++) {
        sx[tid + j * THREADS] = x4[tid + j * THREADS];
    }
    __syncthreads();

    // ---- Phase 1: binary-weight dot product + connection count ----
    const float4* st4 = reinterpret_cast<const float4*>(states + (size_t)o * IN_FEATURES);
    float dot = 0.0f, wsum = 0.0f;
    #pragma unroll
    for (int j = 0; j < F4_PER_THREAD; j++) {
        const int i = tid + j * THREADS;
        float4 s  = st4[i];
        float4 xv = sx[i];
        float w0 = (s.x > 50.0f) ? 1.0f : 0.0f;
        float w1 = (s.y > 50.0f) ? 1.0f : 0.0f;
        float w2 = (s.z > 50.0f) ? 1.0f : 0.0f;
        float w3 = (s.w > 50.0f) ? 1.0f : 0.0f;
        dot  += w0 * xv.x + w1 * xv.y + w2 * xv.z + w3 * xv.w;
        wsum += w0 + w1 + w2 + w3;
    }

    // Warp reduce
    #pragma unroll
    for (int off = 16; off > 0; off >>= 1) {
        dot  += __shfl_xor_sync(0xFFFFFFFFu, dot,  off);
        wsum += __shfl_xor_sync(0xFFFFFFFFu, wsum, off);
    }
    const int lane = tid & 31;
    const int wid  = tid >> 5;
    if (lane == 0) { warp_dot[wid] = dot; warp_wsum[wid] = wsum; }
    __syncthreads();   // the single barrier: partials published

    // All-thread redundant final reduce + epilogue (pure smem + ALU).
    float d = 0.0f, ws = 0.0f;
    #pragma unroll
    for (int w = 0; w < NWARPS; w++) { d += warp_dot[w]; ws += warp_wsum[w]; }
    const float conn    = fmaxf(ws, 5.0f);
    const float current = d * (15.0f * rsqrtf(conn));
    const float v_mem   = mp_o * 0.85f + current;
    const float spike   = (v_mem >= thr_o) ? 1.0f : 0.0f;
    if (tid == 0) {
        const float new_v = v_mem * (1.0f - spike) * 0.1f;
        const float new_t = fminf(fmaxf(thr_o + (spike - 0.1f) * 0.1f, 2.0f), 15.0f);
        out[o]                    = spike;   // spikes
        out[OUT_FEATURES + o]     = new_v;   // new membrane potential
        out[2 * OUT_FEATURES + o] = new_t;   // new adaptive threshold
    }

    // ---- Phase 2: eligibility-trace update (trace now L2-resident) ----
    const float4* tr4 = reinterpret_cast<const float4*>(trace + (size_t)o * IN_FEATURES);
    float4* ot4 = reinterpret_cast<float4*>(out + 3 * (size_t)OUT_FEATURES + (size_t)o * IN_FEATURES);
    #pragma unroll
    for (int j = 0; j < F4_PER_THREAD; j++) {
        const int i = tid + j * THREADS;
        float4 t  = tr4[i];
        float4 xv = sx[i];
        float4 r;
        r.x = fminf(fmaxf(t.x * 0.9f + spike * xv.x, 0.0f), 5.0f);
        r.y = fminf(fmaxf(t.y * 0.9f + spike * xv.y, 0.0f), 5.0f);
        r.z = fminf(fmaxf(t.z * 0.9f + spike * xv.z, 0.0f), 5.0f);
        r.w = fminf(fmaxf(t.w * 0.9f + spike * xv.w, 0.0f), 5.0f);
        __stcs(&ot4[i], r);
    }
}

extern "C" void kernel_launch(void* const* d_in, const int* in_sizes, int n_in,
                              void* d_out, int out_size) {
    const float* x      = (const float*)d_in[0];   // spike_input [8192]
    const float* states = (const float*)d_in[1];   // synapse_states [8192,8192]
    const float* mp     = (const float*)d_in[2];   // membrane_potential [8192]
    const float* thr    = (const float*)d_in[3];   // adaptive_threshold [8192]
    const float* trace  = (const float*)d_in[4];   // eligibility_trace [8192,8192]
    float* out          = (float*)d_out;

    snn_fused_kernel<<<OUT_FEATURES, THREADS>>>(x, states, mp, thr, trace, out);
}

// round 15
// speedup vs baseline: 1.1053x; 1.0059x over previous
#include <cuda_runtime.h>

#define IN_FEATURES 8192
#define OUT_FEATURES 8192
#define THREADS 256
#define NWARPS (THREADS / 32)
#define F4_PER_ROW (IN_FEATURES / 4)          // 2048
#define F4_PER_THREAD (F4_PER_ROW / THREADS)  // 8

__global__ __launch_bounds__(THREADS, 2)
void snn_fused_kernel(const float* __restrict__ x,
                      const float* __restrict__ states,
                      const float* __restrict__ mp,
                      const float* __restrict__ thr,
                      const float* __restrict__ trace,
                      float* __restrict__ out) {
    __shared__ float4 sx[F4_PER_ROW];   // 32 KB staged spike input (once per 2 rows)
    __shared__ float warp_dot0[NWARPS], warp_wsum0[NWARPS];
    __shared__ float warp_dot1[NWARPS], warp_wsum1[NWARPS];

    const int o0  = blockIdx.x * 2;
    const int o1  = o0 + 1;
    const int tid = threadIdx.x;

    // Hoist scalar epilogue inputs for both rows (independent loads).
    const float mp0  = __ldg(&mp[o0]),  mp1  = __ldg(&mp[o1]);
    const float th0  = __ldg(&thr[o0]), th1  = __ldg(&thr[o1]);

    // Stage x once per CTA (amortized over 2 rows).
    const float4* x4 = reinterpret_cast<const float4*>(x);
    #pragma unroll
    for (int j = 0; j < F4_PER_THREAD; j++) {
        sx[tid + j * THREADS] = x4[tid + j * THREADS];
    }
    __syncthreads();

    // ---- Phase 1, row 0 ----
    const float4* st0 = reinterpret_cast<const float4*>(states + (size_t)o0 * IN_FEATURES);
    float dot0 = 0.0f, ws0 = 0.0f;
    #pragma unroll
    for (int j = 0; j < F4_PER_THREAD; j++) {
        const int i = tid + j * THREADS;
        float4 s  = st0[i];
        float4 xv = sx[i];
        float w0 = (s.x > 50.0f) ? 1.0f : 0.0f;
        float w1 = (s.y > 50.0f) ? 1.0f : 0.0f;
        float w2 = (s.z > 50.0f) ? 1.0f : 0.0f;
        float w3 = (s.w > 50.0f) ? 1.0f : 0.0f;
        dot0 += w0 * xv.x + w1 * xv.y + w2 * xv.z + w3 * xv.w;
        ws0  += w0 + w1 + w2 + w3;
    }

    // ---- Phase 1, row 1 (back-to-back: one long read stream) ----
    const float4* st1 = reinterpret_cast<const float4*>(states + (size_t)o1 * IN_FEATURES);
    float dot1 = 0.0f, ws1 = 0.0f;
    #pragma unroll
    for (int j = 0; j < F4_PER_THREAD; j++) {
        const int i = tid + j * THREADS;
        float4 s  = st1[i];
        float4 xv = sx[i];
        float w0 = (s.x > 50.0f) ? 1.0f : 0.0f;
        float w1 = (s.y > 50.0f) ? 1.0f : 0.0f;
        float w2 = (s.z > 50.0f) ? 1.0f : 0.0f;
        float w3 = (s.w > 50.0f) ? 1.0f : 0.0f;
        dot1 += w0 * xv.x + w1 * xv.y + w2 * xv.z + w3 * xv.w;
        ws1  += w0 + w1 + w2 + w3;
    }

    // Warp reduce both rows.
    #pragma unroll
    for (int off = 16; off > 0; off >>= 1) {
        dot0 += __shfl_xor_sync(0xFFFFFFFFu, dot0, off);
        ws0  += __shfl_xor_sync(0xFFFFFFFFu, ws0,  off);
        dot1 += __shfl_xor_sync(0xFFFFFFFFu, dot1, off);
        ws1  += __shfl_xor_sync(0xFFFFFFFFu, ws1,  off);
    }
    const int lane = tid & 31;
    const int wid  = tid >> 5;
    if (lane == 0) {
        warp_dot0[wid] = dot0; warp_wsum0[wid] = ws0;
        warp_dot1[wid] = dot1; warp_wsum1[wid] = ws1;
    }
    __syncthreads();   // ONE barrier for BOTH rows

    // All-thread redundant final reduce + epilogues.
    float d0 = 0.0f, w0s = 0.0f, d1 = 0.0f, w1s = 0.0f;
    #pragma unroll
    for (int w = 0; w < NWARPS; w++) {
        d0 += warp_dot0[w]; w0s += warp_wsum0[w];
        d1 += warp_dot1[w]; w1s += warp_wsum1[w];
    }
    const float v0     = mp0 * 0.85f + d0 * (15.0f * rsqrtf(fmaxf(w0s, 5.0f)));
    const float spike0 = (v0 >= th0) ? 1.0f : 0.0f;
    const float v1     = mp1 * 0.85f + d1 * (15.0f * rsqrtf(fmaxf(w1s, 5.0f)));
    const float spike1 = (v1 >= th1) ? 1.0f : 0.0f;
    if (tid == 0) {
        out[o0]                    = spike0;
        out[OUT_FEATURES + o0]     = v0 * (1.0f - spike0) * 0.1f;
        out[2 * OUT_FEATURES + o0] = fminf(fmaxf(th0 + (spike0 - 0.1f) * 0.1f, 2.0f), 15.0f);
        out[o1]                    = spike1;
        out[OUT_FEATURES + o1]     = v1 * (1.0f - spike1) * 0.1f;
        out[2 * OUT_FEATURES + o1] = fminf(fmaxf(th1 + (spike1 - 0.1f) * 0.1f, 2.0f), 15.0f);
    }

    // ---- Phase 2, row 0 ----
    const float4* tr0 = reinterpret_cast<const float4*>(trace + (size_t)o0 * IN_FEATURES);
    float4* ot0 = reinterpret_cast<float4*>(out + 3 * (size_t)OUT_FEATURES + (size_t)o0 * IN_FEATURES);
    #pragma unroll
    for (int j = 0; j < F4_PER_THREAD; j++) {
        const int i = tid + j * THREADS;
        float4 t  = tr0[i];
        float4 xv = sx[i];
        float4 r;
        r.x = fminf(fmaxf(t.x * 0.9f + spike0 * xv.x, 0.0f), 5.0f);
        r.y = fminf(fmaxf(t.y * 0.9f + spike0 * xv.y, 0.0f), 5.0f);
        r.z = fminf(fmaxf(t.z * 0.9f + spike0 * xv.z, 0.0f), 5.0f);
        r.w = fminf(fmaxf(t.w * 0.9f + spike0 * xv.w, 0.0f), 5.0f);
        __stcs(&ot0[i], r);
    }

    // ---- Phase 2, row 1 ----
    const float4* tr1 = reinterpret_cast<const float4*>(trace + (size_t)o1 * IN_FEATURES);
    float4* ot1 = reinterpret_cast<float4*>(out + 3 * (size_t)OUT_FEATURES + (size_t)o1 * IN_FEATURES);
    #pragma unroll
    for (int j = 0; j < F4_PER_THREAD; j++) {
        const int i = tid + j * THREADS;
        float4 t  = tr1[i];
        float4 xv = sx[i];
        float4 r;
        r.x = fminf(fmaxf(t.x * 0.9f + spike1 * xv.x, 0.0f), 5.0f);
        r.y = fminf(fmaxf(t.y * 0.9f + spike1 * xv.y, 0.0f), 5.0f);
        r.z = fminf(fmaxf(t.z * 0.9f + spike1 * xv.z, 0.0f), 5.0f);
        r.w = fminf(fmaxf(t.w * 0.9f + spike1 * xv.w, 0.0f), 5.0f);
        __stcs(&ot1[i], r);
    }
}

extern "C" void kernel_launch(void* const* d_in, const int* in_sizes, int n_in,
                              void* d_out, int out_size) {
    const float* x      = (const float*)d_in[0];   // spike_input [8192]
    const float* states = (const float*)d_in[1];   // synapse_states [8192,8192]
    const float* mp     = (const float*)d_in[2];   // membrane_potential [8192]
    const float* thr    = (const float*)d_in[3];   // adaptive_threshold [8192]
    const float* trace  = (const float*)d_in[4];   // eligibility_trace [8192,8192]
    float* out          = (float*)d_out;

    snn_fused_kernel<<<OUT_FEATURES / 2, THREADS>>>(x, states, mp, thr, trace, out);
}